// round 8
// baseline (speedup 1.0000x reference)
#include <cuda_runtime.h>
#include <cstdint>

#define N_ATOMS_MAX 50000
#define N_PAIRS_MAX 800000
#define CDIM 64
#define ROW  (3 * CDIM)   // 192 floats per atom
#define SCAN_CHUNK 512
#define MAX_CHUNKS 256    // covers N_ATOMS_MAX / 512

// Static scratch (no allocations allowed).
__device__ float g_agg[N_ATOMS_MAX * ROW];            // 38.4 MB
__device__ int2  g_sorted[N_PAIRS_MAX];               // (j, pair_id) sorted by i
__device__ int   g_hist[N_ATOMS_MAX];
__device__ int   g_off[N_ATOMS_MAX];
__device__ int   g_cursor[N_ATOMS_MAX];
__device__ int   g_bsum[MAX_CHUNKS];

typedef unsigned long long u64;

// ---- packed f32x2 helpers (sm_103a) ---------------------------------------
__device__ __forceinline__ u64 pack2(float a, float b) {
    u64 r; asm("mov.b64 %0, {%1, %2};" : "=l"(r) : "f"(a), "f"(b)); return r;
}
__device__ __forceinline__ void unpack2(u64 v, float& a, float& b) {
    asm("mov.b64 {%0, %1}, %2;" : "=f"(a), "=f"(b) : "l"(v));
}
__device__ __forceinline__ u64 fma2(u64 a, u64 b, u64 c) {
    u64 r; asm("fma.rn.f32x2 %0, %1, %2, %3;" : "=l"(r) : "l"(a), "l"(b), "l"(c)); return r;
}

// ---------------------------------------------------------------------------
// Sort pipeline: histogram -> 3-step exclusive scan -> scatter
// ---------------------------------------------------------------------------
__global__ void hist_kernel(const int* __restrict__ ind, int* __restrict__ hist,
                            int n_pairs) {
    int p = blockIdx.x * blockDim.x + threadIdx.x;
    if (p < n_pairs) atomicAdd(&hist[ind[2 * p]], 1);
}

__global__ void scan1_kernel(const int* __restrict__ hist, int* __restrict__ off,
                             int* __restrict__ bsum, int n) {
    __shared__ int s[SCAN_CHUNK];
    int tid = threadIdx.x;
    int idx = blockIdx.x * SCAN_CHUNK + tid;
    int v = (idx < n) ? hist[idx] : 0;
    s[tid] = v;
    __syncthreads();
#pragma unroll
    for (int o = 1; o < SCAN_CHUNK; o <<= 1) {
        int x = (tid >= o) ? s[tid - o] : 0;
        __syncthreads();
        s[tid] += x;
        __syncthreads();
    }
    if (idx < n) off[idx] = s[tid] - v;          // exclusive within chunk
    if (tid == SCAN_CHUNK - 1) bsum[blockIdx.x] = s[tid];
}

__global__ void scan2_kernel(int* __restrict__ bsum, int nchunks) {
    __shared__ int s[MAX_CHUNKS];
    int tid = threadIdx.x;
    if (tid < nchunks) s[tid] = bsum[tid];
    __syncthreads();
    if (tid == 0) {
        int run = 0;
        for (int i = 0; i < nchunks; i++) { int v = s[i]; s[i] = run; run += v; }
    }
    __syncthreads();
    if (tid < nchunks) bsum[tid] = s[tid];
}

__global__ void scan3_kernel(int* __restrict__ off, int* __restrict__ cursor,
                             const int* __restrict__ bsum, int n) {
    int idx = blockIdx.x * blockDim.x + threadIdx.x;
    if (idx < n) {
        int o = off[idx] + bsum[idx >> 9];   // 512-chunk
        off[idx] = o;
        cursor[idx] = o;
    }
}

__global__ void scatter_kernel(const int* __restrict__ ind, int* __restrict__ cursor,
                               int2* __restrict__ sorted, int n_pairs) {
    int p = blockIdx.x * blockDim.x + threadIdx.x;
    if (p >= n_pairs) return;
    int2 ij = *reinterpret_cast<const int2*>(ind + 2 * p);
    int pos = atomicAdd(&cursor[ij.x], 1);
    sorted[pos] = make_int2(ij.y, p);     // (source atom j, pair id)
}

// ---------------------------------------------------------------------------
// Pair kernel v3: 16-thread group owns one destination atom; walks its sorted
// segment, accumulates 12 floats in registers, writes agg once. No atomics.
// ---------------------------------------------------------------------------
__global__ void __launch_bounds__(256) pair_seg_kernel(
    const int2* __restrict__ sorted,
    const int* __restrict__ off,
    const int* __restrict__ cnt,
    const float* __restrict__ p3,
    const float* __restrict__ i1,
    const float* __restrict__ d3,
    float* __restrict__ agg,
    int n_atoms)
{
    int t = blockIdx.x * blockDim.x + threadIdx.x;
    int a = t >> 4;
    if (a >= n_atoms) return;
    int lane = t & 15;

    int start = off[a];
    int n     = cnt[a];

    float4 acc0 = make_float4(0.f, 0.f, 0.f, 0.f);
    float4 acc1 = acc0, acc2 = acc0;

    int k = 0;
    for (; k + 2 <= n; k += 2) {
        int2 jpA = sorted[start + k];
        int2 jpB = sorted[start + k + 1];

        const float4* pjA = reinterpret_cast<const float4*>(p3 + (size_t)jpA.x * ROW);
        const float4* pjB = reinterpret_cast<const float4*>(p3 + (size_t)jpB.x * ROW);
        float4 gA = *reinterpret_cast<const float4*>(i1 + (size_t)jpA.y * CDIM + lane * 4);
        float4 gB = *reinterpret_cast<const float4*>(i1 + (size_t)jpB.y * CDIM + lane * 4);
        float dA0 = d3[3 * jpA.y + 0], dA1 = d3[3 * jpA.y + 1], dA2 = d3[3 * jpA.y + 2];
        float dB0 = d3[3 * jpB.y + 0], dB1 = d3[3 * jpB.y + 1], dB2 = d3[3 * jpB.y + 2];

        float4 vA0 = pjA[lane], vA1 = pjA[16 + lane], vA2 = pjA[32 + lane];
        float4 vB0 = pjB[lane], vB1 = pjB[16 + lane], vB2 = pjB[32 + lane];

        acc0.x += (vA0.x + dA0) * gA.x;  acc0.y += (vA0.y + dA0) * gA.y;
        acc0.z += (vA0.z + dA0) * gA.z;  acc0.w += (vA0.w + dA0) * gA.w;
        acc1.x += (vA1.x + dA1) * gA.x;  acc1.y += (vA1.y + dA1) * gA.y;
        acc1.z += (vA1.z + dA1) * gA.z;  acc1.w += (vA1.w + dA1) * gA.w;
        acc2.x += (vA2.x + dA2) * gA.x;  acc2.y += (vA2.y + dA2) * gA.y;
        acc2.z += (vA2.z + dA2) * gA.z;  acc2.w += (vA2.w + dA2) * gA.w;

        acc0.x += (vB0.x + dB0) * gB.x;  acc0.y += (vB0.y + dB0) * gB.y;
        acc0.z += (vB0.z + dB0) * gB.z;  acc0.w += (vB0.w + dB0) * gB.w;
        acc1.x += (vB1.x + dB1) * gB.x;  acc1.y += (vB1.y + dB1) * gB.y;
        acc1.z += (vB1.z + dB1) * gB.z;  acc1.w += (vB1.w + dB1) * gB.w;
        acc2.x += (vB2.x + dB2) * gB.x;  acc2.y += (vB2.y + dB2) * gB.y;
        acc2.z += (vB2.z + dB2) * gB.z;  acc2.w += (vB2.w + dB2) * gB.w;
    }
    if (k < n) {
        int2 jp = sorted[start + k];
        const float4* pj = reinterpret_cast<const float4*>(p3 + (size_t)jp.x * ROW);
        float4 g = *reinterpret_cast<const float4*>(i1 + (size_t)jp.y * CDIM + lane * 4);
        float d0 = d3[3 * jp.y + 0], d1 = d3[3 * jp.y + 1], d2 = d3[3 * jp.y + 2];
        float4 v0 = pj[lane], v1 = pj[16 + lane], v2 = pj[32 + lane];
        acc0.x += (v0.x + d0) * g.x;  acc0.y += (v0.y + d0) * g.y;
        acc0.z += (v0.z + d0) * g.z;  acc0.w += (v0.w + d0) * g.w;
        acc1.x += (v1.x + d1) * g.x;  acc1.y += (v1.y + d1) * g.y;
        acc1.z += (v1.z + d1) * g.z;  acc1.w += (v1.w + d1) * g.w;
        acc2.x += (v2.x + d2) * g.x;  acc2.y += (v2.y + d2) * g.y;
        acc2.z += (v2.z + d2) * g.z;  acc2.w += (v2.w + d2) * g.w;
    }

    float4* pa = reinterpret_cast<float4*>(agg + (size_t)a * ROW);
    pa[lane]      = acc0;
    pa[16 + lane] = acc1;
    pa[32 + lane] = acc2;
}

// ---------------------------------------------------------------------------
// Epilogue v3: 16-d x 3-row thread tile. Block = 128 threads = 32 atoms x 4
// d-groups. Per c: 4x LDS.128 (w, 16B-aligned via stride-68 pad) +
// 3x LDS.32 (sA, conflict-free stride 196) -> 24 FFMA2.
// ---------------------------------------------------------------------------
#define ATOMS_PER_BLOCK 32

__global__ void __launch_bounds__(128) gemm_kernel(
    const float* __restrict__ agg,
    const float* __restrict__ W,
    float* __restrict__ p3_new,
    float* __restrict__ dotted,
    int n_atoms)
{
    __shared__ __align__(16) float sWT[CDIM][CDIM + 4];           // stride 68: rows 16B-aligned
    __shared__ __align__(16) float sA[ATOMS_PER_BLOCK][ROW + 4];  // stride 196: 16B-aligned, odd/32 banks

    int tid = threadIdx.x;           // 0..127
    int a0  = blockIdx.x * ATOMS_PER_BLOCK;

    // stage W transposed: sWT[c][d] = W[d*64+c]
    for (int kk = tid; kk < CDIM * CDIM; kk += 128) {
        int d = kk >> 6, c = kk & 63;
        sWT[c][d] = W[kk];
    }
    // stage 32 agg rows (float4)
    {
        const float4* src = reinterpret_cast<const float4*>(agg);
        for (int kk = tid; kk < ATOMS_PER_BLOCK * (ROW / 4); kk += 128) {
            int la = kk / (ROW / 4);
            int e4 = kk - la * (ROW / 4);
            int a  = a0 + la;
            float4 v = (a < n_atoms) ? src[(size_t)a * (ROW / 4) + e4]
                                     : make_float4(0.f, 0.f, 0.f, 0.f);
            *reinterpret_cast<float4*>(&sA[la][e4 * 4]) = v;
        }
    }
    __syncthreads();

    int la = tid >> 2;               // local atom 0..31
    int d0 = (tid & 3) * 16;         // this thread's 16 output channels
    int a  = a0 + la;

    u64 acc[3][8];
#pragma unroll
    for (int x = 0; x < 3; x++)
#pragma unroll
        for (int kk = 0; kk < 8; kk++) acc[x][kk] = 0ull;

#pragma unroll 4
    for (int c = 0; c < CDIM; c++) {
        const ulonglong2* wr = reinterpret_cast<const ulonglong2*>(&sWT[c][d0]);
        ulonglong2 w01 = wr[0], w23 = wr[1], w45 = wr[2], w67 = wr[3];

        float av0 = sA[la][c];
        float av1 = sA[la][CDIM + c];
        float av2 = sA[la][2 * CDIM + c];
        u64 aa0 = pack2(av0, av0);
        u64 aa1 = pack2(av1, av1);
        u64 aa2 = pack2(av2, av2);

        acc[0][0] = fma2(aa0, w01.x, acc[0][0]);
        acc[0][1] = fma2(aa0, w01.y, acc[0][1]);
        acc[0][2] = fma2(aa0, w23.x, acc[0][2]);
        acc[0][3] = fma2(aa0, w23.y, acc[0][3]);
        acc[0][4] = fma2(aa0, w45.x, acc[0][4]);
        acc[0][5] = fma2(aa0, w45.y, acc[0][5]);
        acc[0][6] = fma2(aa0, w67.x, acc[0][6]);
        acc[0][7] = fma2(aa0, w67.y, acc[0][7]);

        acc[1][0] = fma2(aa1, w01.x, acc[1][0]);
        acc[1][1] = fma2(aa1, w01.y, acc[1][1]);
        acc[1][2] = fma2(aa1, w23.x, acc[1][2]);
        acc[1][3] = fma2(aa1, w23.y, acc[1][3]);
        acc[1][4] = fma2(aa1, w45.x, acc[1][4]);
        acc[1][5] = fma2(aa1, w45.y, acc[1][5]);
        acc[1][6] = fma2(aa1, w67.x, acc[1][6]);
        acc[1][7] = fma2(aa1, w67.y, acc[1][7]);

        acc[2][0] = fma2(aa2, w01.x, acc[2][0]);
        acc[2][1] = fma2(aa2, w01.y, acc[2][1]);
        acc[2][2] = fma2(aa2, w23.x, acc[2][2]);
        acc[2][3] = fma2(aa2, w23.y, acc[2][3]);
        acc[2][4] = fma2(aa2, w45.x, acc[2][4]);
        acc[2][5] = fma2(aa2, w45.y, acc[2][5]);
        acc[2][6] = fma2(aa2, w67.x, acc[2][6]);
        acc[2][7] = fma2(aa2, w67.y, acc[2][7]);
    }

    if (a >= n_atoms) return;

    float dot[16];
#pragma unroll
    for (int kk = 0; kk < 16; kk++) dot[kk] = 0.f;

#pragma unroll
    for (int x = 0; x < 3; x++) {
        float s[16];
#pragma unroll
        for (int kk = 0; kk < 8; kk++) {
            unpack2(acc[x][kk], s[2 * kk], s[2 * kk + 1]);
            dot[2 * kk]     += s[2 * kk]     * s[2 * kk];
            dot[2 * kk + 1] += s[2 * kk + 1] * s[2 * kk + 1];
        }
        float* out = p3_new + (size_t)a * ROW + x * CDIM + d0;
#pragma unroll
        for (int q = 0; q < 4; q++)
            *reinterpret_cast<float4*>(out + 4 * q) =
                make_float4(s[4 * q], s[4 * q + 1], s[4 * q + 2], s[4 * q + 3]);
    }
    {
        float* out = dotted + (size_t)a * CDIM + d0;
#pragma unroll
        for (int q = 0; q < 4; q++)
            *reinterpret_cast<float4*>(out + 4 * q) =
                make_float4(dot[4 * q], dot[4 * q + 1], dot[4 * q + 2], dot[4 * q + 3]);
    }
}

// ---------------------------------------------------------------------------
// Inputs (metadata order): ind_2 [P,2] i32, p3 [A,3,64] f32, i1 [P,64] f32,
// d3 [P,3] f32, W [64,64] f32.  Output: p3_new [A,3,64] ++ dotted [A,64].
// ---------------------------------------------------------------------------
extern "C" void kernel_launch(void* const* d_in, const int* in_sizes, int n_in,
                              void* d_out, int out_size)
{
    const int*   ind = (const int*)  d_in[0];
    const float* p3  = (const float*)d_in[1];
    const float* i1  = (const float*)d_in[2];
    const float* d3  = (const float*)d_in[3];
    const float* W   = (const float*)d_in[4];

    int n_pairs = in_sizes[0] / 2;
    int n_atoms = in_sizes[1] / ROW;
    int nchunks = (n_atoms + SCAN_CHUNK - 1) / SCAN_CHUNK;

    float* p3_new = (float*)d_out;
    float* dotted = (float*)d_out + (size_t)n_atoms * ROW;

    float *agg; int *hist, *off, *cursor, *bsum; int2 *sorted;
    cudaGetSymbolAddress((void**)&agg,    g_agg);
    cudaGetSymbolAddress((void**)&hist,   g_hist);
    cudaGetSymbolAddress((void**)&off,    g_off);
    cudaGetSymbolAddress((void**)&cursor, g_cursor);
    cudaGetSymbolAddress((void**)&bsum,   g_bsum);
    cudaGetSymbolAddress((void**)&sorted, g_sorted);

    // --- sort pairs by destination atom ---
    cudaMemsetAsync(hist, 0, n_atoms * sizeof(int));
    hist_kernel<<<(n_pairs + 255) / 256, 256>>>(ind, hist, n_pairs);
    scan1_kernel<<<nchunks, SCAN_CHUNK>>>(hist, off, bsum, n_atoms);
    scan2_kernel<<<1, MAX_CHUNKS>>>(bsum, nchunks);
    scan3_kernel<<<(n_atoms + 255) / 256, 256>>>(off, cursor, bsum, n_atoms);
    scatter_kernel<<<(n_pairs + 255) / 256, 256>>>(ind, cursor, sorted, n_pairs);

    // --- segment accumulation (register-resident, no atomics) ---
    {
        int total = n_atoms * 16;
        pair_seg_kernel<<<(total + 255) / 256, 256>>>(sorted, off, hist,
                                                      p3, i1, d3, agg, n_atoms);
    }

    // --- epilogue GEMM + dot ---
    {
        int blocks = (n_atoms + ATOMS_PER_BLOCK - 1) / ATOMS_PER_BLOCK;
        gemm_kernel<<<blocks, 128>>>(agg, W, p3_new, dotted, n_atoms);
    }
}